// round 17
// speedup vs baseline: 8.1924x; 1.0379x over previous
#include <cuda_runtime.h>
#include <cuda_fp16.h>
#include <math.h>
#include <stdint.h>

// ---------------- problem constants ----------------
#define TOK   2048
#define DIMM  1024
#define NH    16
#define HD    64
#define SEQ   2048
#define NASS  8192
#define NEXP  32
#define FDIM  512
#define DSH   2048

// ---------------- scratch ----------------
__device__ __align__(16) __half g_xnormh[TOK*DIMM];
__device__ __align__(16) __half g_qmh[NH*SEQ*HD];
__device__ __align__(16) __half g_kmh[NH*SEQ*HD];
__device__ __align__(16) unsigned g_vmP[NH*(SEQ/2)*HD];
__device__ __align__(16) __half g_orowsh[TOK*DIMM];
__device__ float g_xffni[TOK*DIMM];
__device__ __align__(16) __half g_xffnh[TOK*DIMM];
__device__ __align__(16) __half g_Gh[NASS*FDIM];
__device__ __align__(16) __half g_slotsh[(size_t)NASS*DIMM];
__device__ __align__(16) __half g_hsh[(size_t)TOK*DSH];
__device__ __align__(16) __half g_shdownh[(size_t)TOK*DIMM];
__device__ __align__(16) float2 g_ropeT[1024*32];
// split-KV attention partials
__device__ __align__(16) float  g_attO[(size_t)256*8192];
__device__ __align__(16) float2 g_attML[256*128];
__device__ float g_scales[NASS];
__device__ int   g_eid[NASS];
__device__ int   g_tokof[NASS];
__device__ int   g_posof[NASS];
__device__ int   g_counts[NEXP];
__device__ int   g_offsets[NEXP];
__device__ int   g_cursors[NEXP];
// K-major packed fp16 weights: Wt[N][K]
__device__ __align__(16) __half g_wqkvT[3072*1024];
__device__ __align__(16) __half g_woT[1024*1024];
__device__ __align__(16) __half g_wupT[(size_t)4096*1024];
__device__ __align__(16) __half g_wdnT[(size_t)1024*2048];
__device__ __align__(16) __half g_wguT[(size_t)32*1024*1024];
__device__ __align__(16) __half g_wdnM[(size_t)32*1024*512];

// ---------------- helpers ----------------
__device__ __forceinline__ unsigned f2h2(float a, float b) {
    __half2 h = __floats2half2_rn(a, b);
    return *reinterpret_cast<unsigned*>(&h);
}
__device__ __forceinline__ void mma16(float c[4], const unsigned a[4], const unsigned b[2]) {
    asm volatile("mma.sync.aligned.m16n8k16.row.col.f32.f16.f16.f32 "
                 "{%0,%1,%2,%3},{%4,%5,%6,%7},{%8,%9},{%0,%1,%2,%3};"
                 : "+f"(c[0]), "+f"(c[1]), "+f"(c[2]), "+f"(c[3])
                 : "r"(a[0]), "r"(a[1]), "r"(a[2]), "r"(a[3]), "r"(b[0]), "r"(b[1]));
}
__device__ __forceinline__ uint32_t s2u(const void* p) {
    uint32_t a;
    asm("{ .reg .u64 t; cvta.to.shared.u64 t, %1; cvt.u32.u64 %0, t; }" : "=r"(a) : "l"(p));
    return a;
}
__device__ __forceinline__ void cpa16(uint32_t dst, const void* src) {
    asm volatile("cp.async.ca.shared.global [%0], [%1], 16;" :: "r"(dst), "l"(src));
}
__device__ __forceinline__ void cpa4(uint32_t dst, const void* src) {
    asm volatile("cp.async.ca.shared.global [%0], [%1], 4;" :: "r"(dst), "l"(src));
}
#define CPA_COMMIT() asm volatile("cp.async.commit_group;")
#define CPA_WAIT1()  asm volatile("cp.async.wait_group 1;")
#define CPA_WAIT0()  asm volatile("cp.async.wait_group 0;")

__device__ __forceinline__ void ldsm4(unsigned* r, uint32_t a) {
    asm volatile("ldmatrix.sync.aligned.m8n8.x4.shared.b16 {%0,%1,%2,%3}, [%4];"
                 : "=r"(r[0]), "=r"(r[1]), "=r"(r[2]), "=r"(r[3]) : "r"(a));
}
__device__ __forceinline__ uint32_t frag_off(int rowBase, int stride, int lane) {
    int lr = lane & 7, lh = (lane >> 3) & 1, lq = lane >> 4;
    return (uint32_t)(((rowBase + lr + lh*8) * stride + lq*4) * 4);
}

__device__ __forceinline__ void compute_tile_ldsm(uint32_t aS, uint32_t bS,
                                                  uint32_t aOff0, uint32_t aOff1,
                                                  const uint32_t* bOff,
                                                  float acc[16][4]) {
    #pragma unroll
    for (int ks = 0; ks < 2; ks++) {
        unsigned a0[4], a1[4], bq[4][4];
        ldsm4(a0, aS + aOff0 + ks*32);
        ldsm4(a1, aS + aOff1 + ks*32);
        #pragma unroll
        for (int p = 0; p < 4; p++) ldsm4(bq[p], bS + bOff[p] + ks*32);
        #pragma unroll
        for (int ni = 0; ni < 8; ni++) {
            unsigned bf[2] = { bq[ni>>1][ni&1], bq[ni>>1][(ni&1)+2] };
            mma16(acc[ni],   a0, bf);
            mma16(acc[8+ni], a1, bf);
        }
    }
}

// ---------------- rope table ----------------
__global__ void __launch_bounds__(256) rope_table() {
    int idx = blockIdx.x*256 + threadIdx.x;    // 32768
    int si = idx >> 5, d = idx & 31;
    float inv = powf(10000.0f, -(float)(2*d) / 64.0f);
    float sn, cs;
    sincosf((float)si * inv, &sn, &cs);
    g_ropeT[idx] = make_float2(cs, sn);
}

// ---------------- transpose-pack ----------------
template<int MODE>
__device__ __forceinline__ void packT_body(const float* __restrict__ W,
                                           __half* __restrict__ Wt,
                                           int K, int N, int k0, int n0, int tid) {
    __shared__ __half tile[32][72];
    int nl = tid & 31, kl = tid >> 5;
    #pragma unroll
    for (int it = 0; it < 8; it++)
        tile[nl][kl + it*8] = __float2half(W[(size_t)(k0 + kl + it*8)*N + n0 + nl]);
    __syncthreads();
    int kq8 = (tid & 7)*8, nr = tid >> 3;
    int c = n0 + nr;
    int drow;
    if (MODE == 0) drow = c;
    else {
        int NHf = N >> 1;
        drow = (c < NHf) ? ((c >> 6)*128 + (c & 63))
                         : (((c - NHf) >> 6)*128 + 64 + ((c - NHf) & 63));
    }
    *(uint4*)&Wt[(size_t)drow*K + k0 + kq8] = *(uint4*)&tile[nr][kq8];
}
__global__ void __launch_bounds__(256) packT(const float* __restrict__ W,
                                             __half* __restrict__ Wt, int K, int N) {
    packT_body<0>(W, Wt, K, N, blockIdx.x*64, blockIdx.y*32, threadIdx.x);
}
__global__ void __launch_bounds__(256) packT_gu(const float* __restrict__ W,
                                                __half* __restrict__ Wt, int K, int N) {
    packT_body<1>(W, Wt, K, N, blockIdx.x*64, blockIdx.y*32, threadIdx.x);
}
__global__ void __launch_bounds__(256) packT_moe(const float* __restrict__ pW,
                                                 const float* __restrict__ fW) {
    __shared__ __half tile[32][72];
    int z = blockIdx.z;
    int sel = z >> 5, e = z & 31;
    const float* W = (e < 16) ? pW + ((size_t)sel*16 + e)      * (size_t)DIMM*FDIM
                              : fW + ((size_t)sel*16 + (e-16)) * (size_t)DIMM*FDIM;
    __half* Wt = g_wguT + (size_t)e*1024*1024;
    int k0 = blockIdx.x*64, n0 = blockIdx.y*32;
    int tid = threadIdx.x;
    int nl = tid & 31, kl = tid >> 5;
    #pragma unroll
    for (int it = 0; it < 8; it++)
        tile[nl][kl + it*8] = __float2half(W[(size_t)(k0 + kl + it*8)*FDIM + n0 + nl]);
    __syncthreads();
    int kq8 = (tid & 7)*8, nr = tid >> 3;
    int c = n0 + nr;
    int drow = (c >> 6)*128 + sel*64 + (c & 63);
    *(uint4*)&Wt[(size_t)drow*DIMM + k0 + kq8] = *(uint4*)&tile[nr][kq8];
}
__global__ void __launch_bounds__(256) conv_moe_down(const float* __restrict__ pW,
                                                     const float* __restrict__ fW) {
    int z = blockIdx.z;
    const float* W = (z < 16) ? pW + ((size_t)2*16 + z)      * (size_t)DIMM*FDIM
                              : fW + ((size_t)2*16 + (z-16)) * (size_t)DIMM*FDIM;
    __half* Wh = g_wdnM + (size_t)z*1024*512;
    int idx = blockIdx.x*256 + threadIdx.x;
    float4 a = ((const float4*)W)[idx*2];
    float4 b = ((const float4*)W)[idx*2 + 1];
    ((uint4*)Wh)[idx] = make_uint4(f2h2(a.x,a.y), f2h2(a.z,a.w), f2h2(b.x,b.y), f2h2(b.z,b.w));
}

// ---------------- dense fp16 GEMM, 3-stage cp.async + ldmatrix ----------------
// OUT 0: float out (+D)   OUT 1: half out   OUT 2: fused swiglu
// OUT 3: fused rope+interleave (QKV GEMM; writes g_qmh/g_kmh/g_vmP directly)
#define GEMM_SMEM (2560 * 2 * 3 * 4)
template<int OUT>
__global__ void __launch_bounds__(256) gemm_h(const __half* __restrict__ A,
                                              const __half* __restrict__ Bt,
                                              void* __restrict__ Cv,
                                              const float* __restrict__ D,
                                              int M, int N, int K) {
    extern __shared__ __align__(16) unsigned smem[];
    unsigned* As = smem;
    unsigned* Bs = smem + 3*2560;
    int tid = threadIdx.x, lane = tid & 31, wid = tid >> 5;
    int g = lane >> 2, t4 = lane & 3;
    int wm = (wid & 3)*32, wn = (wid >> 2)*64;
    size_t rowBase = (size_t)blockIdx.y * 128, colBase = (size_t)blockIdx.x * 128;
    int r_ = tid >> 1, sel = tid & 1;
    int sidx = r_*20 + sel*8;
    const __half* Ag = A  + (rowBase + r_)*K + sel*16;
    const __half* Bg = Bt + (colBase + r_)*K + sel*16;
    uint32_t aB = s2u(As), bB = s2u(Bs);
    uint32_t aOff0 = frag_off(wm, 20, lane), aOff1 = frag_off(wm+16, 20, lane);
    uint32_t bOff[4];
    #pragma unroll
    for (int p = 0; p < 4; p++) bOff[p] = frag_off(wn + p*16, 20, lane);
    int NC = K >> 5;

    auto issue = [&](int cc, int s) {
        uint32_t ad = aB + (s*2560 + sidx)*4;
        cpa16(ad,      Ag + cc*32);
        cpa16(ad + 16, Ag + cc*32 + 8);
        uint32_t bd = bB + (s*2560 + sidx)*4;
        cpa16(bd,      Bg + cc*32);
        cpa16(bd + 16, Bg + cc*32 + 8);
        CPA_COMMIT();
    };

    float acc[16][4];
    #pragma unroll
    for (int i = 0; i < 16; i++)
        #pragma unroll
        for (int j = 0; j < 4; j++) acc[i][j] = 0.f;

    issue(0, 0);
    issue(1, 1);
    for (int c = 0; c < NC; c++) {
        if (c + 2 < NC) CPA_WAIT1(); else CPA_WAIT0();
        __syncthreads();
        int s = c - (c/3)*3;
        compute_tile_ldsm(aB + s*2560*4, bB + s*2560*4, aOff0, aOff1, bOff, acc);
        if (c + 2 < NC) issue(c + 2, (c+2) - ((c+2)/3)*3);
    }
    if (OUT == 3) {
        // fused rope + dual-interleave epilogue; warp covers exactly one head
        int sect = (int)(colBase >> 10);                 // 0=q, 1=k, 2=v
        int cc0 = (int)colBase + wn - sect*1024;
        int h = cc0 >> 6;
        if (sect < 2) {
            __half* dst = sect ? g_kmh : g_qmh;
            #pragma unroll
            for (int mi = 0; mi < 2; mi++) {
                int r0 = (int)rowBase + wm + mi*16 + g;
                #pragma unroll
                for (int ni = 0; ni < 4; ni++) {
                    int d = ni*8 + 2*t4;
                    float* c1 = acc[mi*8+ni];
                    float* c2 = acc[mi*8+ni+4];
                    #pragma unroll
                    for (int rr = 0; rr < 2; rr++) {
                        int r = r0 + rr*8;
                        int si = r & 1023;
                        int t = 2*si + (r >> 10);
                        float2 tb0 = g_ropeT[si*32 + d];
                        float2 tb1 = g_ropeT[si*32 + d + 1];
                        float x10 = c1[rr*2], x11 = c1[rr*2+1];
                        float x20 = c2[rr*2], x21 = c2[rr*2+1];
                        size_t off = ((size_t)h*SEQ + t)*64 + d;
                        *(unsigned*)&dst[off]      = f2h2( x10*tb0.x + x20*tb0.y,
                                                           x11*tb1.x + x21*tb1.y);
                        *(unsigned*)&dst[off + 32] = f2h2(-x10*tb0.y + x20*tb0.x,
                                                          -x11*tb1.y + x21*tb1.x);
                    }
                }
            }
        } else {
            __half* vh = (__half*)g_vmP;
            #pragma unroll
            for (int mi = 0; mi < 2; mi++) {
                int r0 = (int)rowBase + wm + mi*16 + g;
                #pragma unroll
                for (int ni = 0; ni < 8; ni++) {
                    int d = ni*8 + 2*t4;
                    float* c = acc[mi*8+ni];
                    #pragma unroll
                    for (int rr = 0; rr < 2; rr++) {
                        int r = r0 + rr*8;
                        int si = r & 1023;
                        int t = 2*si + (r >> 10);
                        size_t bb = ((size_t)h*1024 + (t >> 1))*64;
                        vh[(bb + d)*2     + (t & 1)] = __float2half(c[rr*2]);
                        vh[(bb + d + 1)*2 + (t & 1)] = __float2half(c[rr*2+1]);
                    }
                }
            }
        }
        return;
    }
    if (OUT == 2) {
        __syncthreads();
        unsigned* sm = smem;
        #pragma unroll
        for (int mi = 0; mi < 2; mi++)
            #pragma unroll
            for (int ni = 0; ni < 8; ni++) {
                float* c = acc[mi*8+ni];
                int r = wm + mi*16 + g;
                int cw = (wn >> 1) + ni*4 + t4;
                sm[r*66 + cw]     = f2h2(c[0], c[1]);
                sm[(r+8)*66 + cw] = f2h2(c[2], c[3]);
            }
        __syncthreads();
        __half* C = (__half*)Cv;
        int outN = N >> 1;
        size_t fBase = colBase >> 1;
        for (int idx = tid; idx < 128*32; idx += 256) {
            int r = idx >> 5, cw = idx & 31;
            float2 gf = __half22float2(*(__half2*)&sm[r*66 + cw]);
            float2 uf = __half22float2(*(__half2*)&sm[r*66 + 32 + cw]);
            float a = gf.x / (1.f + __expf(-gf.x)) * uf.x;
            float b = gf.y / (1.f + __expf(-gf.y)) * uf.y;
            *(unsigned*)&C[(rowBase + r)*outN + fBase + 2*cw] = f2h2(a, b);
        }
        return;
    }
    #pragma unroll
    for (int mi = 0; mi < 2; mi++)
        #pragma unroll
        for (int ni = 0; ni < 8; ni++) {
            float* c = acc[mi*8+ni];
            size_t r0 = rowBase + wm + mi*16 + g;
            size_t c0 = colBase + wn + ni*8 + 2*t4;
            if (OUT == 0) {
                float* C = (float*)Cv;
                size_t o0 = r0*N + c0, o1 = (r0+8)*N + c0;
                if (D) {
                    C[o0] = c[0] + D[o0]; C[o0+1] = c[1] + D[o0+1];
                    C[o1] = c[2] + D[o1]; C[o1+1] = c[3] + D[o1+1];
                } else {
                    C[o0] = c[0]; C[o0+1] = c[1];
                    C[o1] = c[2]; C[o1+1] = c[3];
                }
            } else {
                __half* C = (__half*)Cv;
                *(unsigned*)&C[r0*N + c0]     = f2h2(c[0], c[1]);
                *(unsigned*)&C[(r0+8)*N + c0] = f2h2(c[2], c[3]);
            }
        }
}

// ---------------- MoE gate+up grouped GEMM, fused swiglu -> g_Gh ----------------
__global__ void __launch_bounds__(256) moe_gu_h() {
    extern __shared__ __align__(16) unsigned smem[];
    unsigned* As = smem;
    unsigned* Bs = smem + 3*2560;
    __shared__ int rows[128];
    int e = blockIdx.z;
    int cnt = g_counts[e];
    int rowTile = blockIdx.y * 128;
    if (rowTile >= cnt) return;
    int base = g_offsets[e];
    int colBase = blockIdx.x * 128;
    const __half* Wt = g_wguT + (size_t)e*1024*1024;
    int tid = threadIdx.x;
    if (tid < 128) {
        int rr = rowTile + tid;
        rows[tid] = (rr < cnt) ? g_tokof[base + rr] : 0;
    }
    __syncthreads();
    int lane = tid & 31, wid = tid >> 5;
    int g = lane >> 2, t4 = lane & 3;
    int wm = (wid & 3)*32, wn = (wid >> 2)*64;
    int r_ = tid >> 1, sel = tid & 1;
    int sidx = r_*20 + sel*8;
    const __half* Ag = g_xffnh + (size_t)rows[r_]*DIMM + sel*16;
    const __half* Bg = Wt + (size_t)(colBase + r_)*1024 + sel*16;
    uint32_t aB = s2u(As), bB = s2u(Bs);
    uint32_t aOff0 = frag_off(wm, 20, lane), aOff1 = frag_off(wm+16, 20, lane);
    uint32_t bOff[4];
    #pragma unroll
    for (int p = 0; p < 4; p++) bOff[p] = frag_off(wn + p*16, 20, lane);

    auto issue = [&](int cc, int s) {
        uint32_t ad = aB + (s*2560 + sidx)*4;
        cpa16(ad,      Ag + cc*32);
        cpa16(ad + 16, Ag + cc*32 + 8);
        uint32_t bd = bB + (s*2560 + sidx)*4;
        cpa16(bd,      Bg + cc*32);
        cpa16(bd + 16, Bg + cc*32 + 8);
        CPA_COMMIT();
    };

    float acc[16][4];
    #pragma unroll
    for (int i = 0; i < 16; i++)
        #pragma unroll
        for (int j = 0; j < 4; j++) acc[i][j] = 0.f;

    issue(0, 0);
    issue(1, 1);
    for (int c = 0; c < 32; c++) {
        if (c + 2 < 32) CPA_WAIT1(); else CPA_WAIT0();
        __syncthreads();
        int s = c - (c/3)*3;
        compute_tile_ldsm(aB + s*2560*4, bB + s*2560*4, aOff0, aOff1, bOff, acc);
        if (c + 2 < 32) issue(c + 2, (c+2) - ((c+2)/3)*3);
    }
    __syncthreads();
    unsigned* sm = smem;
    #pragma unroll
    for (int mi = 0; mi < 2; mi++)
        #pragma unroll
        for (int ni = 0; ni < 8; ni++) {
            float* c = acc[mi*8+ni];
            int r = wm + mi*16 + g;
            int cw = (wn >> 1) + ni*4 + t4;
            sm[r*66 + cw]     = f2h2(c[0], c[1]);
            sm[(r+8)*66 + cw] = f2h2(c[2], c[3]);
        }
    __syncthreads();
    int fBase = colBase >> 1;
    for (int idx = tid; idx < 128*32; idx += 256) {
        int r = idx >> 5, cw = idx & 31;
        if (rowTile + r >= cnt) continue;
        float2 gf = __half22float2(*(__half2*)&sm[r*66 + cw]);
        float2 uf = __half22float2(*(__half2*)&sm[r*66 + 32 + cw]);
        float a = gf.x / (1.f + __expf(-gf.x)) * uf.x;
        float b = gf.y / (1.f + __expf(-gf.y)) * uf.y;
        *(unsigned*)&g_Gh[(size_t)(base + rowTile + r)*FDIM + fBase + 2*cw] = f2h2(a, b);
    }
}

// ---------------- MoE down grouped GEMM ----------------
__global__ void __launch_bounds__(256) moe_down_h() {
    extern __shared__ __align__(16) unsigned smem[];
    unsigned* As = smem;
    unsigned* Bs = smem + 3*2560;
    int e = blockIdx.z;
    int cnt = g_counts[e];
    int rowTile = blockIdx.y * 128;
    if (rowTile >= cnt) return;
    int base = g_offsets[e];
    int colBase = blockIdx.x * 128;
    const __half* W = g_wdnM + (size_t)e*1024*512;
    int tid = threadIdx.x, lane = tid & 31, wid = tid >> 5;
    int g = lane >> 2, t4 = lane & 3;
    int wm = (wid & 3)*32, wn = (wid >> 2)*64;
    int r_ = tid >> 1, sel = tid & 1;
    int sidx = r_*20 + sel*8;
    int arow = base + rowTile + r_;
    if (arow > NASS - 1) arow = NASS - 1;
    const __half* Ag = g_Gh + (size_t)arow*FDIM + sel*16;
    const __half* Bg = W + (size_t)(colBase + r_)*FDIM + sel*16;
    uint32_t aB = s2u(As), bB = s2u(Bs);
    uint32_t aOff0 = frag_off(wm, 20, lane), aOff1 = frag_off(wm+16, 20, lane);
    uint32_t bOff[4];
    #pragma unroll
    for (int p = 0; p < 4; p++) bOff[p] = frag_off(wn + p*16, 20, lane);

    auto issue = [&](int cc, int s) {
        uint32_t ad = aB + (s*2560 + sidx)*4;
        cpa16(ad,      Ag + cc*32);
        cpa16(ad + 16, Ag + cc*32 + 8);
        uint32_t bd = bB + (s*2560 + sidx)*4;
        cpa16(bd,      Bg + cc*32);
        cpa16(bd + 16, Bg + cc*32 + 8);
        CPA_COMMIT();
    };

    float acc[16][4];
    #pragma unroll
    for (int i = 0; i < 16; i++)
        #pragma unroll
        for (int j = 0; j < 4; j++) acc[i][j] = 0.f;

    issue(0, 0);
    issue(1, 1);
    for (int c = 0; c < 16; c++) {
        if (c + 2 < 16) CPA_WAIT1(); else CPA_WAIT0();
        __syncthreads();
        int s = c - (c/3)*3;
        compute_tile_ldsm(aB + s*2560*4, bB + s*2560*4, aOff0, aOff1, bOff, acc);
        if (c + 2 < 16) issue(c + 2, (c+2) - ((c+2)/3)*3);
    }
    #pragma unroll
    for (int mi = 0; mi < 2; mi++)
        #pragma unroll
        for (int ni = 0; ni < 8; ni++) {
            float* c = acc[mi*8+ni];
            int r = rowTile + wm + mi*16 + g;
            int cc = colBase + wn + ni*8 + 2*t4;
            if (r < cnt)
                *(unsigned*)&g_slotsh[(size_t)(base+r)*DIMM + cc] = f2h2(c[0], c[1]);
            if (r + 8 < cnt)
                *(unsigned*)&g_slotsh[(size_t)(base+r+8)*DIMM + cc] = f2h2(c[2], c[3]);
        }
}

// ---------------- rmsnorm (half out) ----------------
__global__ void rmsnorm_h(const float* __restrict__ x, const float* __restrict__ w,
                          __half* __restrict__ out) {
    int r = blockIdx.x;
    const float* xr = x + (size_t)r*DIMM;
    __shared__ float red[8];
    float s = 0.f;
    for (int d = threadIdx.x; d < DIMM; d += 256) { float v = xr[d]; s += v*v; }
    #pragma unroll
    for (int o = 16; o; o >>= 1) s += __shfl_xor_sync(0xffffffffu, s, o);
    if ((threadIdx.x & 31) == 0) red[threadIdx.x >> 5] = s;
    __syncthreads();
    if (threadIdx.x == 0) {
        float t = 0.f;
        #pragma unroll
        for (int i = 0; i < 8; i++) t += red[i];
        red[0] = rsqrtf(t / (float)DIMM + 1e-5f);
    }
    __syncthreads();
    float rms = red[0];
    for (int d = threadIdx.x; d < DIMM; d += 256)
        out[(size_t)r*DIMM + d] = __float2half(xr[d] * rms * w[d]);
}

// ---------------- fused rmsnorm + router ----------------
__global__ void __launch_bounds__(256) rmsnorm_router(
    const float* __restrict__ x, const float* __restrict__ w,
    const float* __restrict__ pkeys, const float* __restrict__ fkeys,
    const float* __restrict__ pbias, const float* __restrict__ fbias,
    const int* __restrict__ pidx, const float* __restrict__ pval,
    const int* __restrict__ fidx, const float* __restrict__ fval,
    __half* __restrict__ out) {
    int tok = blockIdx.x, tid = threadIdx.x;
    const float* xr = x + (size_t)tok*DIMM;
    __shared__ float red[8];
    __shared__ __half xs[DIMM];
    __shared__ float part[16][17];
    __shared__ float logit[16];
    float s = 0.f;
    for (int d = tid; d < DIMM; d += 256) { float v = xr[d]; s += v*v; }
    #pragma unroll
    for (int o = 16; o; o >>= 1) s += __shfl_xor_sync(0xffffffffu, s, o);
    if ((tid & 31) == 0) red[tid >> 5] = s;
    __syncthreads();
    if (tid == 0) {
        float t = 0.f;
        #pragma unroll
        for (int i = 0; i < 8; i++) t += red[i];
        red[0] = rsqrtf(t / (float)DIMM + 1e-5f);
    }
    __syncthreads();
    float rms = red[0];
    for (int d = tid; d < DIMM; d += 256) {
        __half hv = __float2half(xr[d] * rms * w[d]);
        xs[d] = hv;
        out[(size_t)tok*DIMM + d] = hv;
    }
    __syncthreads();
    bool isf = tok >= 1024;
    const float* keys = isf ? fkeys : pkeys;
    int e = tid & 15, ch = tid >> 4;
    float sl = 0.f;
    int d0 = ch * 64;
    for (int d = d0; d < d0 + 64; d++)
        sl = fmaf(__half2float(xs[d]), keys[d*16 + e], sl);
    part[ch][e] = sl;
    __syncthreads();
    if (tid < 16) {
        float t = 0.f;
        #pragma unroll
        for (int c = 0; c < 16; c++) t += part[c][tid];
        logit[tid] = t;
    }
    __syncthreads();
    if (tid == 0) {
        int lt = isf ? tok - 1024 : tok;
        const int*   idx  = isf ? fidx  : pidx;
        const float* val  = isf ? fval  : pval;
        const float* bias = isf ? fbias : pbias;
        float sc[4]; int id[4]; float sum = 0.f;
        #pragma unroll
        for (int k = 0; k < 4; k++) {
            int ix = idx[lt*4 + k];
            float v = val[lt*4 + k] + logit[ix] + bias[ix];
            float s2 = 1.f / (1.f + expf(-v));
            sc[k] = s2; sum += s2;
            id[k] = ix + (isf ? 16 : 0);
        }
        #pragma unroll
        for (int k = 0; k < 4; k++) {
            g_scales[tok*4 + k] = sc[k] / sum;
            g_eid[tok*4 + k] = id[k];
            atomicAdd(&g_counts[id[k]], 1);
        }
    }
}

// ---------------- fp16 flash attention (split-KV load-balanced) ----------------
#define ATT_SMEM_W (4608*4)
__global__ void __launch_bounds__(256) attn_h() {
    extern __shared__ __align__(16) unsigned asm_[];
    unsigned* Qs = asm_;
    unsigned* Ps = asm_ + 4608;
    unsigned* Ks = asm_ + 9216;
    unsigned* Vt = asm_ + 13824;
    int i = blockIdx.x, h = blockIdx.y;
    int b, split, nsplit;
    if (i < 16) { b = 15 - (i >> 1); split = i & 1; nsplit = 2; }
    else        { b = 23 - i;        split = 0;     nsplit = 1; }
    int t0 = b * 128;
    int ntot = (t0 + 128) >> 6;
    int half = ntot >> 1;
    int tlo = (nsplit == 2 && split == 1) ? half : 0;
    int thi = (nsplit == 2 && split == 0) ? half : ntot;
    int tid = threadIdx.x, lane = tid & 31, wid = tid >> 5;
    int g = lane >> 2, t4 = lane & 3;
    int wm = wid * 16;
    uint32_t qB = s2u(Qs), kB = s2u(Ks), pB = s2u(Ps), vB = s2u(Vt);
    uint32_t aOffQ = frag_off(wm, 36, lane);
    uint32_t bOffK[4];
    #pragma unroll
    for (int p = 0; p < 4; p++) bOffK[p] = frag_off(p*16, 36, lane);

    const __half* qb = g_qmh + ((size_t)h*SEQ + t0)*64;
    for (int ii = tid; ii < 128*8; ii += 256) {
        int r = ii >> 3, j = ii & 7;
        *(uint4*)&Qs[r*36 + j*4] = ((const uint4*)(qb + (size_t)r*64))[j];
    }

    auto issueKV = [&](int kt, int s) {
        const __half* kb = g_kmh + ((size_t)h*SEQ + kt)*64;
        #pragma unroll
        for (int it = 0; it < 2; it++) {
            int ii = tid + it*256;
            int r = ii >> 3, j = ii & 7;
            cpa16(kB + (s*2304 + r*36 + j*4)*4, (const uint4*)(kb + (size_t)r*64) + j);
        }
        const unsigned* vp = g_vmP + ((size_t)h*1024 + (kt >> 1))*64;
        #pragma unroll
        for (int it = 0; it < 8; it++) {
            int w = tid + it*256;
            int d = w & 63, p = w >> 6;
            cpa4(vB + (s*2304 + d*36 + p)*4, vp + (size_t)p*64 + d);
        }
        CPA_COMMIT();
    };

    float o[8][4];
    #pragma unroll
    for (int n = 0; n < 8; n++)
        #pragma unroll
        for (int j = 0; j < 4; j++) o[n][j] = 0.f;
    float m0 = -1e30f, m1 = -1e30f, l0 = 0.f, l1 = 0.f;
    int row0 = t0 + wm + g, row1 = row0 + 8;
    int wmax = t0 + wm + 15;

    issueKV(tlo << 6, tlo & 1);
    for (int it = tlo; it < thi; it++) {
        int kt = it << 6;
        if (it + 1 < thi) { issueKV((it+1) << 6, (it+1) & 1); CPA_WAIT1(); }
        else CPA_WAIT0();
        __syncthreads();
        if (kt <= wmax) {
            uint32_t kBs = kB + ((it & 1)*2304)*4;
            uint32_t vBs = vB + ((it & 1)*2304)*4;

            float s[8][4];
            #pragma unroll
            for (int n = 0; n < 8; n++)
                #pragma unroll
                for (int j = 0; j < 4; j++) s[n][j] = 0.f;
            #pragma unroll
            for (int ks = 0; ks < 4; ks++) {
                unsigned aq[4], bq[4][4];
                ldsm4(aq, qB + aOffQ + ks*32);
                #pragma unroll
                for (int p = 0; p < 4; p++) ldsm4(bq[p], kBs + bOffK[p] + ks*32);
                #pragma unroll
                for (int n = 0; n < 8; n++) {
                    unsigned bf[2] = { bq[n>>1][n&1], bq[n>>1][(n&1)+2] };
                    mma16(s[n], aq, bf);
                }
            }
            float mx0 = -1e30f, mx1 = -1e30f;
            #pragma unroll
            for (int n = 0; n < 8; n++) {
                int c0 = kt + n*8 + 2*t4, c1 = c0 + 1;
                s[n][0] = (c0 <= row0) ? s[n][0]*0.125f : -1e30f;
                s[n][1] = (c1 <= row0) ? s[n][1]*0.125f : -1e30f;
                s[n][2] = (c0 <= row1) ? s[n][2]*0.125f : -1e30f;
                s[n][3] = (c1 <= row1) ? s[n][3]*0.125f : -1e30f;
                mx0 = fmaxf(mx0, fmaxf(s[n][0], s[n][1]));
                mx1 = fmaxf(mx1, fmaxf(s[n][2], s[n][3]));
            }
            mx0 = fmaxf(mx0, __shfl_xor_sync(0xffffffffu, mx0, 1));
            mx0 = fmaxf(mx0, __shfl_xor_sync(0xffffffffu, mx0, 2));
            mx1 = fmaxf(mx1, __shfl_xor_sync(0xffffffffu, mx1, 1));
            mx1 = fmaxf(mx1, __shfl_xor_sync(0xffffffffu, mx1, 2));
            float nm0 = fmaxf(m0, mx0), nm1 = fmaxf(m1, mx1);
            float cor0 = __expf(m0 - nm0), cor1 = __expf(m1 - nm1);
            m0 = nm0; m1 = nm1;
            l0 *= cor0; l1 *= cor1;
            float sum0 = 0.f, sum1 = 0.f;
            #pragma unroll
            for (int n = 0; n < 8; n++) {
                float p00 = __expf(s[n][0] - nm0), p01 = __expf(s[n][1] - nm0);
                float p10 = __expf(s[n][2] - nm1), p11 = __expf(s[n][3] - nm1);
                sum0 += p00 + p01; sum1 += p10 + p11;
                Ps[(wm+g)*36 + n*4 + t4]   = f2h2(p00, p01);
                Ps[(wm+g+8)*36 + n*4 + t4] = f2h2(p10, p11);
                #pragma unroll
                for (int j = 0; j < 2; j++) { o[n][j] *= cor0; o[n][2+j] *= cor1; }
            }
            sum0 += __shfl_xor_sync(0xffffffffu, sum0, 1);
            sum0 += __shfl_xor_sync(0xffffffffu, sum0, 2);
            sum1 += __shfl_xor_sync(0xffffffffu, sum1, 1);
            sum1 += __shfl_xor_sync(0xffffffffu, sum1, 2);
            l0 += sum0; l1 += sum1;
            __syncwarp();

            #pragma unroll
            for (int ks = 0; ks < 4; ks++) {
                unsigned ap[4], bq[4][4];
                ldsm4(ap, pB + aOffQ + ks*32);
                #pragma unroll
                for (int p = 0; p < 4; p++) ldsm4(bq[p], vBs + bOffK[p] + ks*32);
                #pragma unroll
                for (int n = 0; n < 8; n++) {
                    unsigned bf[2] = { bq[n>>1][n&1], bq[n>>1][(n&1)+2] };
                    mma16(o[n], ap, bf);
                }
            }
        }
        __syncthreads();
    }

    if (nsplit == 1) {
        float inv0 = 1.f / l0, inv1 = 1.f / l1;
        int tok0 = (row0 & 1)*1024 + (row0 >> 1);
        int tok1 = (row1 & 1)*1024 + (row1 >> 1);
        #pragma unroll
        for (int n = 0; n < 8; n++) {
            int col = h*64 + n*8 + 2*t4;
            *(unsigned*)&g_orowsh[(size_t)tok0*DIMM + col] = f2h2(o[n][0]*inv0, o[n][1]*inv0);
            *(unsigned*)&g_orowsh[(size_t)tok1*DIMM + col] = f2h2(o[n][2]*inv1, o[n][3]*inv1);
        }
    } else {
        size_t pidxg = (size_t)((h*8 + (b-8))*2 + split);
        float* oP = g_attO + pidxg*8192;
        float2* mlP = g_attML + pidxg*128;
        int lr0 = wm + g, lr1 = lr0 + 8;
        #pragma unroll
        for (int n = 0; n < 8; n++) {
            int col = n*8 + 2*t4;
            *(float2*)&oP[lr0*64 + col] = make_float2(o[n][0], o[n][1]);
            *(float2*)&oP[lr1*64 + col] = make_float2(o[n][2], o[n][3]);
        }
        if (t4 == 0) {
            mlP[lr0] = make_float2(m0, l0);
            mlP[lr1] = make_float2(m1, l1);
        }
    }
}

// merge split-KV partials for query tiles b=8..15
__global__ void __launch_bounds__(256) attn_merge() {
    int bb = blockIdx.x;
    int h = blockIdx.y;
    int t0 = (8 + bb) * 128;
    size_t base = (size_t)((h*8 + bb)*2);
    const float* o0 = g_attO + base*8192;
    const float* o1 = o0 + 8192;
    const float2* ml0 = g_attML + base*128;
    const float2* ml1 = ml0 + 128;
    for (int idx = threadIdx.x; idx < 128*32; idx += 256) {
        int r = idx >> 5, cw = (idx & 31)*2;
        float2 a = ml0[r], c = ml1[r];
        float m = fmaxf(a.x, c.x);
        float w0 = __expf(a.x - m), w1 = __expf(c.x - m);
        float invl = 1.f / (a.y*w0 + c.y*w1);
        float x0 = (o0[r*64 + cw]   * w0 + o1[r*64 + cw]   * w1) * invl;
        float x1 = (o0[r*64 + cw+1] * w0 + o1[r*64 + cw+1] * w1) * invl;
        int row = t0 + r;
        int tok = (row & 1)*1024 + (row >> 1);
        *(unsigned*)&g_orowsh[(size_t)tok*DIMM + h*64 + cw] = f2h2(x0, x1);
    }
}

__global__ void zero32_kernel() {
    int i = threadIdx.x;
    if (i < NEXP) { g_counts[i] = 0; g_cursors[i] = 0; }
}

// fused prefix + scatter: single block, 256 threads
__global__ void __launch_bounds__(256) prefix_scatter_kernel() {
    __shared__ int soff[NEXP];
    if (threadIdx.x == 0) {
        int acc = 0;
        for (int e = 0; e < NEXP; e++) { soff[e] = acc; g_offsets[e] = acc; acc += g_counts[e]; }
    }
    __syncthreads();
    for (int a = threadIdx.x; a < NASS; a += 256) {
        int e = g_eid[a];
        int p = soff[e] + atomicAdd(&g_cursors[e], 1);
        g_tokof[p] = a >> 2;
        g_posof[a] = p;
    }
}

__global__ void combine_kernel(float* __restrict__ y) {
    int tok = blockIdx.x;
    __shared__ int pos[4];
    __shared__ float sc[4];
    if (threadIdx.x < 4) {
        pos[threadIdx.x] = g_posof[tok*4 + threadIdx.x];
        sc[threadIdx.x]  = g_scales[tok*4 + threadIdx.x];
    }
    __syncthreads();
    for (int d = threadIdx.x; d < DIMM; d += 256) {
        float v = g_xffni[(size_t)tok*DIMM + d]
                + __half2float(g_shdownh[(size_t)tok*DIMM + d]);
        #pragma unroll
        for (int k = 0; k < 4; k++)
            v = fmaf(sc[k], __half2float(g_slotsh[(size_t)pos[k]*DIMM + d]), v);
        y[(size_t)tok*DIMM + d] = v;
    }
}

// ---------------- launch ----------------
extern "C" void kernel_launch(void* const* d_in, const int* in_sizes, int n_in,
                              void* d_out, int out_size) {
    const float* x_input  = (const float*)d_in[0];
    const int*   p_idx    = (const int*)  d_in[1];
    const float* p_val    = (const float*)d_in[2];
    const int*   f_idx    = (const int*)  d_in[3];
    const float* f_val    = (const float*)d_in[4];
    const float* attn_nw  = (const float*)d_in[5];
    const float* ffn_nw   = (const float*)d_in[6];
    const float* W_attn   = (const float*)d_in[7];
    const float* W_attn_o = (const float*)d_in[8];
    const float* ffn_up   = (const float*)d_in[9];
    const float* ffn_down = (const float*)d_in[10];
    const float* pW       = (const float*)d_in[11];
    const float* fW       = (const float*)d_in[12];
    const float* pkeys    = (const float*)d_in[13];
    const float* fkeys    = (const float*)d_in[14];
    const float* pbias    = (const float*)d_in[15];
    const float* fbias    = (const float*)d_in[16];
    float* out = (float*)d_out;

    __half *xnormh, *orowsh, *xffnh, *hsh, *shdownh;
    __half *wqkvT, *woT, *wupT, *wdnT;
    float *xffni;
    cudaGetSymbolAddress((void**)&xnormh, g_xnormh);
    cudaGetSymbolAddress((void**)&orowsh, g_orowsh);
    cudaGetSymbolAddress((void**)&xffni,  g_xffni);
    cudaGetSymbolAddress((void**)&xffnh,  g_xffnh);
    cudaGetSymbolAddress((void**)&hsh,    g_hsh);
    cudaGetSymbolAddress((void**)&shdownh, g_shdownh);
    cudaGetSymbolAddress((void**)&wqkvT,  g_wqkvT);
    cudaGetSymbolAddress((void**)&woT,    g_woT);
    cudaGetSymbolAddress((void**)&wupT,   g_wupT);
    cudaGetSymbolAddress((void**)&wdnT,   g_wdnT);

    static cudaStream_t s1 = nullptr, s2 = nullptr;
    static cudaEvent_t evFork, evZero, evQKVp, evWo, evWup, evMoeP, evXffn, evSh;
    static bool init_done = false;
    if (!init_done) {
        cudaFuncSetAttribute(attn_h, cudaFuncAttributeMaxDynamicSharedMemorySize,
                             ATT_SMEM_W * 4);
        cudaFuncSetAttribute(gemm_h<0>, cudaFuncAttributeMaxDynamicSharedMemorySize, GEMM_SMEM);
        cudaFuncSetAttribute(gemm_h<1>, cudaFuncAttributeMaxDynamicSharedMemorySize, GEMM_SMEM);
        cudaFuncSetAttribute(gemm_h<2>, cudaFuncAttributeMaxDynamicSharedMemorySize, GEMM_SMEM);
        cudaFuncSetAttribute(gemm_h<3>, cudaFuncAttributeMaxDynamicSharedMemorySize, GEMM_SMEM);
        cudaFuncSetAttribute(moe_gu_h, cudaFuncAttributeMaxDynamicSharedMemorySize, GEMM_SMEM);
        cudaFuncSetAttribute(moe_down_h, cudaFuncAttributeMaxDynamicSharedMemorySize, GEMM_SMEM);
        cudaStreamCreateWithFlags(&s1, cudaStreamNonBlocking);
        cudaStreamCreateWithFlags(&s2, cudaStreamNonBlocking);
        cudaEventCreateWithFlags(&evFork, cudaEventDisableTiming);
        cudaEventCreateWithFlags(&evZero, cudaEventDisableTiming);
        cudaEventCreateWithFlags(&evQKVp, cudaEventDisableTiming);
        cudaEventCreateWithFlags(&evWo,   cudaEventDisableTiming);
        cudaEventCreateWithFlags(&evWup,  cudaEventDisableTiming);
        cudaEventCreateWithFlags(&evMoeP, cudaEventDisableTiming);
        cudaEventCreateWithFlags(&evXffn, cudaEventDisableTiming);
        cudaEventCreateWithFlags(&evSh,   cudaEventDisableTiming);
        init_done = true;
    }

    // fork side stream s1: zero + rope table + all weight packing
    cudaEventRecord(evFork, 0);
    cudaStreamWaitEvent(s1, evFork, 0);
    zero32_kernel<<<1, 32, 0, s1>>>();
    cudaEventRecord(evZero, s1);
    rope_table<<<128, 256, 0, s1>>>();
    packT<<<dim3(16, 96),  256, 0, s1>>>(W_attn,   wqkvT, DIMM, 3*DIMM);
    cudaEventRecord(evQKVp, s1);
    packT<<<dim3(16, 32),  256, 0, s1>>>(W_attn_o, woT,   DIMM, DIMM);
    cudaEventRecord(evWo, s1);
    packT_gu<<<dim3(16, 128), 256, 0, s1>>>(ffn_up, wupT, DIMM, 2*DSH);
    packT<<<dim3(32, 32),  256, 0, s1>>>(ffn_down, wdnT,  DSH,  DIMM);
    cudaEventRecord(evWup, s1);
    packT_moe<<<dim3(16, 16, 64), 256, 0, s1>>>(pW, fW);
    conv_moe_down<<<dim3(256, 1, 32), 256, 0, s1>>>(pW, fW);
    cudaEventRecord(evMoeP, s1);

    // main stream: attention block (QKV GEMM fuses rope+interleave)
    rmsnorm_h<<<TOK, 256>>>(x_input, attn_nw, xnormh);
    cudaStreamWaitEvent(0, evQKVp, 0);
    gemm_h<3><<<dim3(24, 16), 256, GEMM_SMEM>>>(xnormh, wqkvT, nullptr, nullptr, TOK, 3*DIMM, DIMM);
    attn_h<<<dim3(24, NH), 256, ATT_SMEM_W*4>>>();
    attn_merge<<<dim3(8, NH), 256>>>();
    cudaStreamWaitEvent(0, evWo, 0);
    gemm_h<0><<<dim3(8, 16), 256, GEMM_SMEM>>>(orowsh, woT, xffni, x_input, TOK, DIMM, DIMM);
    cudaStreamWaitEvent(0, evZero, 0);
    rmsnorm_router<<<TOK, 256>>>(xffni, ffn_nw, pkeys, fkeys, pbias, fbias,
                                 p_idx, p_val, f_idx, f_val, xffnh);
    cudaEventRecord(evXffn, 0);

    // s2: full shared-expert branch (up + down), overlaps MoE chain
    cudaStreamWaitEvent(s2, evXffn, 0);
    cudaStreamWaitEvent(s2, evWup, 0);
    gemm_h<2><<<dim3(32, 16), 256, GEMM_SMEM, s2>>>(xffnh, wupT, hsh, nullptr, TOK, 2*DSH, DIMM);
    gemm_h<1><<<dim3(8, 16), 256, GEMM_SMEM, s2>>>(hsh, wdnT, shdownh, nullptr, TOK, DIMM, DSH);
    cudaEventRecord(evSh, s2);

    // main: routing + grouped MoE
    prefix_scatter_kernel<<<1, 256>>>();
    cudaStreamWaitEvent(0, evMoeP, 0);
    moe_gu_h<<<dim3(8, 16, NEXP), 256, GEMM_SMEM>>>();
    moe_down_h<<<dim3(8, 16, NEXP), 256, GEMM_SMEM>>>();
    // final combine joins s2 and adds shared-expert output
    cudaStreamWaitEvent(0, evSh, 0);
    combine_kernel<<<TOK, 256>>>(out);
}